// round 7
// baseline (speedup 1.0000x reference)
#include <cuda_runtime.h>
#include <cuda_fp16.h>
#include <math.h>
#include <stdint.h>

#define BB 256
#define HH 1024
#define TT 128
#define FF 512

// GEMM tiling: CTA 64(M) x 128(N), KC=32 per stage, 4 stages, 256 threads (8 warps 2x4)
#define KC 32
#define NSTG 4
#define OFF_A  0
#define OFF_B  4096
#define STAGE_BYTES 12288
#define SMEM_TOTAL (NSTG * STAGE_BYTES)   // 49152
#define NCTA 128

// ---------------- device scratch (static, no runtime alloc) ------------------
__device__ __half g_wsum[4096 * 1024];      // [n=4j+g][k] = (W+U)^T gate-interleaved
__device__ __half g_wcat[4096 * 2048];      // t=0: K = [W;U]
__device__ __half g_wd[512 * 1024];         // [f][k]
__device__ __half g_xcat[256 * 2048];       // [b][x0,h0]
__device__ __half g_xa[256 * 1024];         // ping
__device__ __half g_xb[256 * 1024];         // pong
__device__ __half g_seq[(size_t)BB * TT * HH];  // [b*T+t][k]
__device__ float g_c[BB * HH];
__device__ unsigned g_bar_count;            // zero-init; self-resets each barrier
__device__ unsigned g_bar_gen;              // monotonic across launches (baselined per launch)

// ---------------- helpers -----------------------------------------------------
__device__ __forceinline__ uint32_t smem_u32(const void* p) {
    uint32_t a;
    asm("{ .reg .u64 t; cvta.to.shared.u64 t, %1; cvt.u32.u64 %0, t; }" : "=r"(a) : "l"(p));
    return a;
}
__device__ __forceinline__ uint32_t sw64(uint32_t o) { return o ^ ((o >> 3) & 0x30); }
__device__ __forceinline__ float sigm(float x) { return 1.0f / (1.0f + expf(-x)); }

#define CP_ASYNC16(sm, gp) \
    asm volatile("cp.async.cg.shared.global [%0], [%1], 16;" :: "r"(sm), "l"(gp) : "memory")
#define CP_COMMIT() asm volatile("cp.async.commit_group;" ::: "memory")
template <int N>
__device__ __forceinline__ void cp_wait() {
    asm volatile("cp.async.wait_group %0;" :: "n"(N) : "memory");
}

__device__ __forceinline__ void ldsm4(uint32_t* r, uint32_t addr) {
    asm volatile("ldmatrix.sync.aligned.m8n8.x4.shared.b16 {%0,%1,%2,%3}, [%4];"
                 : "=r"(r[0]), "=r"(r[1]), "=r"(r[2]), "=r"(r[3]) : "r"(addr));
}
__device__ __forceinline__ void mma16816(float* c, const uint32_t* a, uint32_t b0, uint32_t b1) {
    asm volatile("mma.sync.aligned.m16n8k16.row.col.f32.f16.f16.f32 "
                 "{%0,%1,%2,%3},{%4,%5,%6,%7},{%8,%9},{%0,%1,%2,%3};"
                 : "+f"(c[0]), "+f"(c[1]), "+f"(c[2]), "+f"(c[3])
                 : "r"(a[0]), "r"(a[1]), "r"(a[2]), "r"(a[3]), "r"(b0), "r"(b1));
}

// ---------------- grid barrier (128 co-resident CTAs) -------------------------
__device__ __forceinline__ void grid_barrier(unsigned target) {
    __syncthreads();                                  // all CTA writes ordered before arrival
    if (threadIdx.x == 0) {
        __threadfence();                              // release: CTA's writes visible gpu-wide
        unsigned a = atomicAdd(&g_bar_count, 1u);
        if (a == NCTA - 1) {
            atomicExch(&g_bar_count, 0u);             // reset for next barrier
            __threadfence();
            atomicAdd(&g_bar_gen, 1u);                // release the pack
        } else {
            volatile unsigned* pg = &g_bar_gen;
            while (*pg < target) {}
            __threadfence();                          // acquire
        }
    }
    __syncthreads();
}

// ---------------- pipelined GEMM mainloop ------------------------------------
// A[m][k] fp16, B[n][k] fp16, row-major, leading dim ldk. C += A*B^T.
__device__ __forceinline__ void issue_load(uint32_t sbase, int s, int c,
                                           const __half* A, int am0,
                                           const __half* B, int bn0, int ldk, int tid) {
    const uint32_t st = sbase + s * STAGE_BYTES;
    const int k0 = c * KC;
    const int ar = tid >> 2, ac = tid & 3;
    const size_t ga = (size_t)(am0 + ar) * ldk + k0 + ac * 8;
    const uint32_t sa = sw64((uint32_t)(ar * 64 + ac * 16));
    CP_ASYNC16(st + OFF_A + sa, A + ga);
#pragma unroll
    for (int it = 0; it < 2; ++it) {
        const int idx = it * 256 + tid;
        const int br = idx >> 2, bc = idx & 3;
        const size_t gb = (size_t)(bn0 + br) * ldk + k0 + bc * 8;
        const uint32_t sb = sw64((uint32_t)(br * 64 + bc * 16));
        CP_ASYNC16(st + OFF_B + sb, B + gb);
    }
    CP_COMMIT();
}

__device__ __forceinline__ void gemm_main(uint32_t sbase,
                                          const __half* A, int am0,
                                          const __half* B, int bn0, int ldk, int nch,
                                          float C[2][4][4]) {
    const int tid = threadIdx.x;
    const int lane = tid & 31, wid = tid >> 5;
    const int wm = wid & 1, wn = wid >> 1;

    issue_load(sbase, 0, 0, A, am0, B, bn0, ldk, tid);
    issue_load(sbase, 1, 1, A, am0, B, bn0, ldk, tid);
    issue_load(sbase, 2, 2, A, am0, B, bn0, ldk, tid);

    const int lrow = lane & 15;
    const int lkb = (lane >> 4) * 16;

    for (int c = 0; c < nch; ++c) {
        const int s = c & (NSTG - 1);
        // tail-safe waits: guarantee group c complete before consuming stage c
        if (c < nch - 2)      cp_wait<2>();
        else if (c == nch - 2) cp_wait<1>();
        else                   cp_wait<0>();
        __syncthreads();
        const uint32_t st = sbase + s * STAGE_BYTES;
#pragma unroll
        for (int h = 0; h < 2; ++h) {
            uint32_t ah[2][4], bh[2][4];
#pragma unroll
            for (int mi = 0; mi < 2; ++mi) {
                const uint32_t off = sw64((uint32_t)((wm * 32 + mi * 16 + lrow) * 64 + h * 32 + lkb));
                ldsm4(ah[mi], st + OFF_A + off);
            }
#pragma unroll
            for (int nj = 0; nj < 2; ++nj) {
                const uint32_t off = sw64((uint32_t)((wn * 32 + nj * 16 + lrow) * 64 + h * 32 + lkb));
                ldsm4(bh[nj], st + OFF_B + off);
            }
#pragma unroll
            for (int mi = 0; mi < 2; ++mi)
#pragma unroll
                for (int nt = 0; nt < 4; ++nt) {
                    const int gsel = nt >> 1, ssel = nt & 1;
                    mma16816(C[mi][nt], ah[mi], bh[gsel][ssel], bh[gsel][ssel + 2]);
                }
        }
        if (c + 3 < nch)
            issue_load(sbase, (c + 3) & (NSTG - 1), c + 3, A, am0, B, bn0, ldk, tid);
    }
}

// ---------------- persistent LSTM scan kernel ---------------------------------
// grid 128 CTAs (32 n-tiles x 4 m-tiles), 256 threads; all T steps in one launch.
__global__ __launch_bounds__(256)
void lstm_scan(const __half* __restrict__ xcat, const __half* __restrict__ wcat,
               const __half* __restrict__ wsum,
               const float* __restrict__ bias, const float* __restrict__ c0,
               float* __restrict__ cbuf,
               __half* __restrict__ x0buf, __half* __restrict__ x1buf) {
    extern __shared__ char smem[];
    const uint32_t sbase = smem_u32(smem);

    const int ntile = blockIdx.x & 31;
    const int mtile = blockIdx.x >> 5;
    const int am0 = mtile * 64;
    const int bn0 = ntile * 128;

    const int lane = threadIdx.x & 31, wid = threadIdx.x >> 5;
    const int wm = wid & 1, wn = wid >> 1;
    const bool odd = lane & 1;

    const unsigned G = *(volatile unsigned*)&g_bar_gen;   // pre-launch baseline

    for (int t = 0; t < TT; ++t) {
        const __half* A  = (t == 0) ? xcat : ((t & 1) ? x0buf : x1buf);   // read xb[(t-1)&1]
        const __half* B  = (t == 0) ? wcat : wsum;
        const int ldk    = (t == 0) ? 2048 : HH;
        const int nch    = ldk / KC;
        const float* cin = (t == 0) ? c0 : cbuf;
        __half* xnext    = (t & 1) ? x1buf : x0buf;                        // write xb[t&1]

        float C[2][4][4];
#pragma unroll
        for (int a = 0; a < 2; ++a)
#pragma unroll
            for (int bq = 0; bq < 4; ++bq)
#pragma unroll
                for (int d = 0; d < 4; ++d) C[a][bq][d] = 0.0f;

        gemm_main(sbase, A, am0, B, bn0, ldk, nch, C);

#pragma unroll
        for (int mi = 0; mi < 2; ++mi)
#pragma unroll
            for (int nt = 0; nt < 4; ++nt) {
                float* c = C[mi][nt];
                const float t0 = __shfl_xor_sync(0xFFFFFFFFu, c[0], 1);
                const float t1 = __shfl_xor_sync(0xFFFFFFFFu, c[1], 1);
                const float t2 = __shfl_xor_sync(0xFFFFFFFFu, c[2], 1);
                const float t3 = __shfl_xor_sync(0xFFFFFFFFu, c[3], 1);
                float zi, zf, zg, zo;
                int rofs;
                if (!odd) { zi = c[0]; zf = c[1]; zg = t0; zo = t1; rofs = 0; }
                else      { zi = t2;  zf = t3;  zg = c[2]; zo = c[3]; rofs = 8; }
                const int b = am0 + wm * 32 + mi * 16 + (lane >> 2) + rofs;
                const int nbase = bn0 + wn * 32 + nt * 8;
                const int j = (nbase >> 2) + ((lane & 3) >> 1);
                zi += bias[j];
                zf += bias[HH + j];
                zg += bias[2 * HH + j];
                zo += bias[3 * HH + j];
                const float cold = cin[b * HH + j];
                const float cn = sigm(zf) * cold + sigm(zi) * tanhf(zg);
                const float hn = sigm(zo) * tanhf(cn);
                cbuf[b * HH + j] = cn;
                const __half hh = __float2half(hn);
                xnext[b * HH + j] = hh;
                g_seq[((size_t)b * TT + t) * HH + j] = hh;
            }

        if (t < TT - 1) grid_barrier(G + (unsigned)t + 1u);
    }
}

// ---------------- dense emission ----------------------------------------------
// grid (4 n-tiles, 512 m-tiles): out[m][f] = seq[m] . wd[f] + bd[f]
__global__ __launch_bounds__(256)
void dense_mma(const float* __restrict__ bd, float* __restrict__ out) {
    extern __shared__ char smem[];
    const uint32_t sbase = smem_u32(smem);
    float C[2][4][4];
#pragma unroll
    for (int a = 0; a < 2; ++a)
#pragma unroll
        for (int bq = 0; bq < 4; ++bq)
#pragma unroll
            for (int d = 0; d < 4; ++d) C[a][bq][d] = 0.0f;

    const int am0 = blockIdx.y * 64;
    const int bn0 = blockIdx.x * 128;
    gemm_main(sbase, g_seq, am0, g_wd, bn0, HH, HH / KC, C);

    const int lane = threadIdx.x & 31, wid = threadIdx.x >> 5;
    const int wm = wid & 1, wn = wid >> 1;

#pragma unroll
    for (int mi = 0; mi < 2; ++mi)
#pragma unroll
        for (int nt = 0; nt < 4; ++nt) {
            const float* c = C[mi][nt];
            const int n = bn0 + wn * 32 + nt * 8 + 2 * (lane & 3);
            const int r = am0 + wm * 32 + mi * 16 + (lane >> 2);
            float2 v0 = {c[0] + bd[n], c[1] + bd[n + 1]};
            float2 v1 = {c[2] + bd[n], c[3] + bd[n + 1]};
            *reinterpret_cast<float2*>(out + (size_t)r * FF + n) = v0;
            *reinterpret_cast<float2*>(out + (size_t)(r + 8) * FF + n) = v1;
        }
}

// ---------------- prep kernels -------------------------------------------------
// wsum: out[n][k] with n = 4j+g, val = W[k][g*1024+j] + U[k][g*1024+j]
__global__ void prep_wsum(const float* __restrict__ W, const float* __restrict__ U) {
    __shared__ float tl[32][33];
    const int n0 = blockIdx.x * 32, k0 = blockIdx.y * 32;
    const int tx = threadIdx.x, ty = threadIdx.y;
    const int n = n0 + tx;
    const int col = ((n & 3) << 10) | (n >> 2);
    for (int kk = ty; kk < 32; kk += 8)
        tl[tx][kk] = W[(size_t)(k0 + kk) * 4096 + col] + U[(size_t)(k0 + kk) * 4096 + col];
    __syncthreads();
    for (int nn = ty; nn < 32; nn += 8)
        g_wsum[(size_t)(n0 + nn) * 1024 + k0 + tx] = __float2half(tl[nn][tx]);
}

// wcat: out[n][k2], k2<1024 -> W, else U
__global__ void prep_wcat(const float* __restrict__ W, const float* __restrict__ U) {
    __shared__ float tl[32][33];
    const int n0 = blockIdx.x * 32, k0 = blockIdx.y * 32;
    const int tx = threadIdx.x, ty = threadIdx.y;
    const int n = n0 + tx;
    const int col = ((n & 3) << 10) | (n >> 2);
    const float* S = (k0 < 1024) ? W : U;
    const int kbase = (k0 < 1024) ? k0 : (k0 - 1024);
    for (int kk = ty; kk < 32; kk += 8)
        tl[tx][kk] = S[(size_t)(kbase + kk) * 4096 + col];
    __syncthreads();
    for (int nn = ty; nn < 32; nn += 8)
        g_wcat[(size_t)(n0 + nn) * 2048 + k0 + tx] = __float2half(tl[nn][tx]);
}

// wd: out[f][k] = Wd[k][f]
__global__ void prep_wd(const float* __restrict__ Wd) {
    __shared__ float tl[32][33];
    const int n0 = blockIdx.x * 32, k0 = blockIdx.y * 32;
    const int tx = threadIdx.x, ty = threadIdx.y;
    for (int kk = ty; kk < 32; kk += 8)
        tl[tx][kk] = Wd[(size_t)(k0 + kk) * 512 + n0 + tx];
    __syncthreads();
    for (int nn = ty; nn < 32; nn += 8)
        g_wd[(size_t)(n0 + nn) * 1024 + k0 + tx] = __float2half(tl[nn][tx]);
}

// xcat: [256][2048] = [x0 | h0]
__global__ void prep_xc(const float* __restrict__ x0, const float* __restrict__ h0) {
    const int i = blockIdx.x * blockDim.x + threadIdx.x;
    const int m = i >> 11, k = i & 2047;
    const float v = (k < 1024) ? x0[m * 1024 + k] : h0[m * 1024 + k - 1024];
    g_xcat[i] = __float2half(v);
}

// ---------------- launch --------------------------------------------------------
extern "C" void kernel_launch(void* const* d_in, const int* in_sizes, int n_in,
                              void* d_out, int out_size) {
    const float* x0 = (const float*)d_in[0];
    const float* h0 = (const float*)d_in[1];
    const float* c0 = (const float*)d_in[2];
    const float* W  = (const float*)d_in[3];
    const float* U  = (const float*)d_in[4];
    const float* bi = (const float*)d_in[5];
    const float* Wd = (const float*)d_in[6];
    const float* bd = (const float*)d_in[7];
    float* out = (float*)d_out;

    static bool attr_done = false;
    if (!attr_done) {
        cudaFuncSetAttribute(lstm_scan, cudaFuncAttributeMaxDynamicSharedMemorySize, SMEM_TOTAL);
        cudaFuncSetAttribute(dense_mma, cudaFuncAttributeMaxDynamicSharedMemorySize, SMEM_TOTAL);
        attr_done = true;
    }

    void* p;
    cudaGetSymbolAddress(&p, g_wsum);  __half* wsum = (__half*)p;
    cudaGetSymbolAddress(&p, g_wcat);  __half* wcat = (__half*)p;
    cudaGetSymbolAddress(&p, g_xcat);  __half* xc   = (__half*)p;
    __half* xb0; __half* xb1;
    cudaGetSymbolAddress(&p, g_xa);    xb0 = (__half*)p;
    cudaGetSymbolAddress(&p, g_xb);    xb1 = (__half*)p;
    cudaGetSymbolAddress(&p, g_c);     float* cbuf = (float*)p;

    dim3 tb(32, 8);
    prep_wsum<<<dim3(128, 32), tb>>>(W, U);
    prep_wcat<<<dim3(128, 64), tb>>>(W, U);
    prep_wd<<<dim3(16, 32), tb>>>(Wd);
    prep_xc<<<2048, 256>>>(x0, h0);

    lstm_scan<<<NCTA, 256, SMEM_TOTAL>>>(xc, wcat, wsum, bi, c0, cbuf, xb0, xb1);

    dense_mma<<<dim3(4, 512), 256, SMEM_TOTAL>>>(bd, out);
}

// round 8
// speedup vs baseline: 2.3205x; 2.3205x over previous
#include <cuda_runtime.h>
#include <cuda_fp16.h>
#include <math.h>
#include <stdint.h>

#define BB 256
#define HH 1024
#define TT 128
#define FF 512

// GEMM tiling: CTA 64(M) x 128(N), KC=32 per stage, 4 stages, 256 threads (8 warps 2x4)
#define KC 32
#define NSTG 4
#define OFF_A  0
#define OFF_B  4096
#define STAGE_BYTES 12288
#define SMEM_TOTAL (NSTG * STAGE_BYTES)   // 49152
#define NCTA 128

// ---------------- device scratch (static, no runtime alloc) ------------------
__device__ __half g_wsum[4096 * 1024];      // [n=4j+g][k] = (W+U)^T gate-interleaved
__device__ __half g_wcat[4096 * 2048];      // t=0: K = [W;U]
__device__ __half g_wd[512 * 1024];         // [f][k]
__device__ __half g_xcat[256 * 2048];       // [b][x0,h0]
__device__ __half g_xa[256 * 1024];         // ping
__device__ __half g_xb[256 * 1024];         // pong
__device__ __half g_seq[(size_t)BB * TT * HH];  // [b*T+t][k]
__device__ unsigned g_bar_count;            // zero-init; self-resets each barrier
__device__ unsigned g_bar_gen;              // monotonic across launches (baselined per launch)

// ---------------- helpers -----------------------------------------------------
__device__ __forceinline__ uint32_t smem_u32(const void* p) {
    uint32_t a;
    asm("{ .reg .u64 t; cvta.to.shared.u64 t, %1; cvt.u32.u64 %0, t; }" : "=r"(a) : "l"(p));
    return a;
}
__device__ __forceinline__ uint32_t sw64(uint32_t o) { return o ^ ((o >> 3) & 0x30); }
__device__ __forceinline__ float sigm(float x) {
    return __fdividef(1.0f, 1.0f + __expf(-x));
}
__device__ __forceinline__ float tanh_(float x) {
    const float e = __expf(-2.0f * fabsf(x));
    const float t = __fdividef(1.0f - e, 1.0f + e);
    return (x < 0.0f) ? -t : t;
}

#define CP_ASYNC16(sm, gp) \
    asm volatile("cp.async.cg.shared.global [%0], [%1], 16;" :: "r"(sm), "l"(gp) : "memory")
#define CP_COMMIT() asm volatile("cp.async.commit_group;" ::: "memory")
template <int N>
__device__ __forceinline__ void cp_wait() {
    asm volatile("cp.async.wait_group %0;" :: "n"(N) : "memory");
}

__device__ __forceinline__ void ldsm4(uint32_t* r, uint32_t addr) {
    asm volatile("ldmatrix.sync.aligned.m8n8.x4.shared.b16 {%0,%1,%2,%3}, [%4];"
                 : "=r"(r[0]), "=r"(r[1]), "=r"(r[2]), "=r"(r[3]) : "r"(addr));
}
__device__ __forceinline__ void mma16816(float* c, const uint32_t* a, uint32_t b0, uint32_t b1) {
    asm volatile("mma.sync.aligned.m16n8k16.row.col.f32.f16.f16.f32 "
                 "{%0,%1,%2,%3},{%4,%5,%6,%7},{%8,%9},{%0,%1,%2,%3};"
                 : "+f"(c[0]), "+f"(c[1]), "+f"(c[2]), "+f"(c[3])
                 : "r"(a[0]), "r"(a[1]), "r"(a[2]), "r"(a[3]), "r"(b0), "r"(b1));
}

// ---------------- grid barrier (128 co-resident CTAs) -------------------------
__device__ __forceinline__ void grid_barrier(unsigned target) {
    __syncthreads();
    if (threadIdx.x == 0) {
        __threadfence();
        unsigned a = atomicAdd(&g_bar_count, 1u);
        if (a == NCTA - 1) {
            atomicExch(&g_bar_count, 0u);
            __threadfence();
            atomicAdd(&g_bar_gen, 1u);
        } else {
            volatile unsigned* pg = &g_bar_gen;
            while (*pg < target) {}
            __threadfence();
        }
    }
    __syncthreads();
}

// ---------------- pipelined GEMM mainloop ------------------------------------
// A[m][k] fp16, B[n][k] fp16, row-major, leading dim ldk. C += A*B^T.
__device__ __forceinline__ void issue_load(uint32_t sbase, int s, int c,
                                           const __half* A, int am0,
                                           const __half* B, int bn0, int ldk, int tid) {
    const uint32_t st = sbase + s * STAGE_BYTES;
    const int k0 = c * KC;
    const int ar = tid >> 2, ac = tid & 3;
    const size_t ga = (size_t)(am0 + ar) * ldk + k0 + ac * 8;
    const uint32_t sa = sw64((uint32_t)(ar * 64 + ac * 16));
    CP_ASYNC16(st + OFF_A + sa, A + ga);
#pragma unroll
    for (int it = 0; it < 2; ++it) {
        const int idx = it * 256 + tid;
        const int br = idx >> 2, bc = idx & 3;
        const size_t gb = (size_t)(bn0 + br) * ldk + k0 + bc * 8;
        const uint32_t sb = sw64((uint32_t)(br * 64 + bc * 16));
        CP_ASYNC16(st + OFF_B + sb, B + gb);
    }
    CP_COMMIT();
}

__device__ __forceinline__ void gemm_main(uint32_t sbase,
                                          const __half* A, int am0,
                                          const __half* B, int bn0, int ldk, int nch,
                                          float C[2][4][4]) {
    const int tid = threadIdx.x;
    const int lane = tid & 31, wid = tid >> 5;
    const int wm = wid & 1, wn = wid >> 1;

    issue_load(sbase, 0, 0, A, am0, B, bn0, ldk, tid);
    issue_load(sbase, 1, 1, A, am0, B, bn0, ldk, tid);
    issue_load(sbase, 2, 2, A, am0, B, bn0, ldk, tid);

    const int lrow = lane & 15;
    const int lkb = (lane >> 4) * 16;

    for (int c = 0; c < nch; ++c) {
        const int s = c & (NSTG - 1);
        if (c < nch - 2)       cp_wait<2>();
        else if (c == nch - 2) cp_wait<1>();
        else                   cp_wait<0>();
        __syncthreads();
        const uint32_t st = sbase + s * STAGE_BYTES;
#pragma unroll
        for (int h = 0; h < 2; ++h) {
            uint32_t ah[2][4], bh[2][4];
#pragma unroll
            for (int mi = 0; mi < 2; ++mi) {
                const uint32_t off = sw64((uint32_t)((wm * 32 + mi * 16 + lrow) * 64 + h * 32 + lkb));
                ldsm4(ah[mi], st + OFF_A + off);
            }
#pragma unroll
            for (int nj = 0; nj < 2; ++nj) {
                const uint32_t off = sw64((uint32_t)((wn * 32 + nj * 16 + lrow) * 64 + h * 32 + lkb));
                ldsm4(bh[nj], st + OFF_B + off);
            }
#pragma unroll
            for (int mi = 0; mi < 2; ++mi)
#pragma unroll
                for (int nt = 0; nt < 4; ++nt) {
                    const int gsel = nt >> 1, ssel = nt & 1;
                    mma16816(C[mi][nt], ah[mi], bh[gsel][ssel], bh[gsel][ssel + 2]);
                }
        }
        if (c + 3 < nch)
            issue_load(sbase, (c + 3) & (NSTG - 1), c + 3, A, am0, B, bn0, ldk, tid);
    }
}

// ---------------- persistent LSTM scan kernel ---------------------------------
// grid 128 CTAs (32 n-tiles x 4 m-tiles), 256 threads; all T steps in one launch.
// Cell state c lives in registers (fixed thread mapping across steps).
// h output staged through smem -> coalesced 16B stores.
#define HSPAD 36   // halves per staged row (64B data + 8B pad, bank-spread)

__global__ __launch_bounds__(256)
void lstm_scan(const __half* __restrict__ xcat, const __half* __restrict__ wcat,
               const __half* __restrict__ wsum,
               const float* __restrict__ bias, const float* __restrict__ c0,
               __half* __restrict__ x0buf, __half* __restrict__ x1buf) {
    extern __shared__ char smem[];
    const uint32_t sbase = smem_u32(smem);
    __half* HS = reinterpret_cast<__half*>(smem);   // staging, aliases stage 0

    const int ntile = blockIdx.x & 31;
    const int mtile = blockIdx.x >> 5;
    const int am0 = mtile * 64;
    const int bn0 = ntile * 128;
    const int j0 = ntile * 32;                      // 32 j-columns per CTA

    const int tid = threadIdx.x;
    const int lane = tid & 31, wid = tid >> 5;
    const int wm = wid & 1, wn = wid >> 1;
    const bool odd = lane & 1;

    // per-thread fixed (b, j) map for the 8 epilogue elements
    int bmap[2], jmap[4];
#pragma unroll
    for (int mi = 0; mi < 2; ++mi)
        bmap[mi] = am0 + wm * 32 + mi * 16 + (lane >> 2) + (odd ? 8 : 0);
#pragma unroll
    for (int nt = 0; nt < 4; ++nt)
        jmap[nt] = (bn0 >> 2) + wn * 8 + nt * 2 + ((lane & 3) >> 1);

    // bias cached in registers (4 j-values x 4 gates)
    float b_i[4], b_f[4], b_g[4], b_o[4];
#pragma unroll
    for (int nt = 0; nt < 4; ++nt) {
        b_i[nt] = bias[jmap[nt]];
        b_f[nt] = bias[HH + jmap[nt]];
        b_g[nt] = bias[2 * HH + jmap[nt]];
        b_o[nt] = bias[3 * HH + jmap[nt]];
    }
    // cell state in registers
    float creg[2][4];
#pragma unroll
    for (int mi = 0; mi < 2; ++mi)
#pragma unroll
        for (int nt = 0; nt < 4; ++nt)
            creg[mi][nt] = c0[bmap[mi] * HH + jmap[nt]];

    const unsigned G = *(volatile unsigned*)&g_bar_gen;   // pre-launch baseline
    unsigned tgt = G;

    for (int t = 0; t < TT; ++t) {
        const __half* A = (t == 0) ? xcat : ((t & 1) ? x0buf : x1buf);
        const __half* B = (t == 0) ? wcat : wsum;
        const int ldk   = (t == 0) ? 2048 : HH;
        const int nch   = ldk / KC;
        __half* xnext   = (t & 1) ? x1buf : x0buf;

        float C[2][4][4];
#pragma unroll
        for (int a = 0; a < 2; ++a)
#pragma unroll
            for (int bq = 0; bq < 4; ++bq)
#pragma unroll
                for (int d = 0; d < 4; ++d) C[a][bq][d] = 0.0f;

        gemm_main(sbase, A, am0, B, bn0, ldk, nch, C);
        __syncthreads();                      // all stages consumed before HS reuse

#pragma unroll
        for (int mi = 0; mi < 2; ++mi)
#pragma unroll
            for (int nt = 0; nt < 4; ++nt) {
                float* c = C[mi][nt];
                const float t0 = __shfl_xor_sync(0xFFFFFFFFu, c[0], 1);
                const float t1 = __shfl_xor_sync(0xFFFFFFFFu, c[1], 1);
                const float t2 = __shfl_xor_sync(0xFFFFFFFFu, c[2], 1);
                const float t3 = __shfl_xor_sync(0xFFFFFFFFu, c[3], 1);
                float zi, zf, zg, zo;
                if (!odd) { zi = c[0]; zf = c[1]; zg = t0; zo = t1; }
                else      { zi = t2;  zf = t3;  zg = c[2]; zo = c[3]; }
                zi += b_i[nt]; zf += b_f[nt]; zg += b_g[nt]; zo += b_o[nt];
                const float cn = sigm(zf) * creg[mi][nt] + sigm(zi) * tanh_(zg);
                const float hn = sigm(zo) * tanh_(cn);
                creg[mi][nt] = cn;
                const int rl = bmap[mi] - am0;             // 0..63
                const int cl = jmap[nt] - j0;              // 0..31
                HS[rl * HSPAD + cl] = __float2half(hn);
            }
        __syncthreads();

        // coalesced copy: 64 rows x 64B; thread i -> row i>>2, 16B chunk i&3
        {
            const int row = tid >> 2, q = tid & 3;
            const uint32_t* src = reinterpret_cast<const uint32_t*>(HS + row * HSPAD) + q * 4;
            uint4 v;
            v.x = src[0]; v.y = src[1]; v.z = src[2]; v.w = src[3];
            const int b = am0 + row;
            *reinterpret_cast<uint4*>(xnext + (size_t)b * HH + j0 + q * 8) = v;
            *reinterpret_cast<uint4*>(g_seq + ((size_t)b * TT + t) * HH + j0 + q * 8) = v;
        }

        if (t < TT - 1) { ++tgt; grid_barrier(tgt); }
    }
}

// ---------------- dense emission ----------------------------------------------
// grid (4 n-tiles, 512 m-tiles): out[m][f] = seq[m] . wd[f] + bd[f]
__global__ __launch_bounds__(256)
void dense_mma(const float* __restrict__ bd, float* __restrict__ out) {
    extern __shared__ char smem[];
    const uint32_t sbase = smem_u32(smem);
    float C[2][4][4];
#pragma unroll
    for (int a = 0; a < 2; ++a)
#pragma unroll
        for (int bq = 0; bq < 4; ++bq)
#pragma unroll
            for (int d = 0; d < 4; ++d) C[a][bq][d] = 0.0f;

    const int am0 = blockIdx.y * 64;
    const int bn0 = blockIdx.x * 128;
    gemm_main(sbase, g_seq, am0, g_wd, bn0, HH, HH / KC, C);

    const int lane = threadIdx.x & 31, wid = threadIdx.x >> 5;
    const int wm = wid & 1, wn = wid >> 1;

#pragma unroll
    for (int mi = 0; mi < 2; ++mi)
#pragma unroll
        for (int nt = 0; nt < 4; ++nt) {
            const float* c = C[mi][nt];
            const int n = bn0 + wn * 32 + nt * 8 + 2 * (lane & 3);
            const int r = am0 + wm * 32 + mi * 16 + (lane >> 2);
            float2 v0 = {c[0] + bd[n], c[1] + bd[n + 1]};
            float2 v1 = {c[2] + bd[n], c[3] + bd[n + 1]};
            *reinterpret_cast<float2*>(out + (size_t)r * FF + n) = v0;
            *reinterpret_cast<float2*>(out + (size_t)(r + 8) * FF + n) = v1;
        }
}

// ---------------- prep kernels -------------------------------------------------
// wsum: out[n][k] with n = 4j+g, val = W[k][g*1024+j] + U[k][g*1024+j]
__global__ void prep_wsum(const float* __restrict__ W, const float* __restrict__ U) {
    __shared__ float tl[32][33];
    const int n0 = blockIdx.x * 32, k0 = blockIdx.y * 32;
    const int tx = threadIdx.x, ty = threadIdx.y;
    const int n = n0 + tx;
    const int col = ((n & 3) << 10) | (n >> 2);
    for (int kk = ty; kk < 32; kk += 8)
        tl[tx][kk] = W[(size_t)(k0 + kk) * 4096 + col] + U[(size_t)(k0 + kk) * 4096 + col];
    __syncthreads();
    for (int nn = ty; nn < 32; nn += 8)
        g_wsum[(size_t)(n0 + nn) * 1024 + k0 + tx] = __float2half(tl[nn][tx]);
}

// wcat: out[n][k2], k2<1024 -> W, else U
__global__ void prep_wcat(const float* __restrict__ W, const float* __restrict__ U) {
    __shared__ float tl[32][33];
    const int n0 = blockIdx.x * 32, k0 = blockIdx.y * 32;
    const int tx = threadIdx.x, ty = threadIdx.y;
    const int n = n0 + tx;
    const int col = ((n & 3) << 10) | (n >> 2);
    const float* S = (k0 < 1024) ? W : U;
    const int kbase = (k0 < 1024) ? k0 : (k0 - 1024);
    for (int kk = ty; kk < 32; kk += 8)
        tl[tx][kk] = S[(size_t)(kbase + kk) * 4096 + col];
    __syncthreads();
    for (int nn = ty; nn < 32; nn += 8)
        g_wcat[(size_t)(n0 + nn) * 2048 + k0 + tx] = __float2half(tl[nn][tx]);
}

// wd: out[f][k] = Wd[k][f]
__global__ void prep_wd(const float* __restrict__ Wd) {
    __shared__ float tl[32][33];
    const int n0 = blockIdx.x * 32, k0 = blockIdx.y * 32;
    const int tx = threadIdx.x, ty = threadIdx.y;
    for (int kk = ty; kk < 32; kk += 8)
        tl[tx][kk] = Wd[(size_t)(k0 + kk) * 512 + n0 + tx];
    __syncthreads();
    for (int nn = ty; nn < 32; nn += 8)
        g_wd[(size_t)(n0 + nn) * 1024 + k0 + tx] = __float2half(tl[nn][tx]);
}

// xcat: [256][2048] = [x0 | h0]
__global__ void prep_xc(const float* __restrict__ x0, const float* __restrict__ h0) {
    const int i = blockIdx.x * blockDim.x + threadIdx.x;
    const int m = i >> 11, k = i & 2047;
    const float v = (k < 1024) ? x0[m * 1024 + k] : h0[m * 1024 + k - 1024];
    g_xcat[i] = __float2half(v);
}

// ---------------- launch --------------------------------------------------------
extern "C" void kernel_launch(void* const* d_in, const int* in_sizes, int n_in,
                              void* d_out, int out_size) {
    const float* x0 = (const float*)d_in[0];
    const float* h0 = (const float*)d_in[1];
    const float* c0 = (const float*)d_in[2];
    const float* W  = (const float*)d_in[3];
    const float* U  = (const float*)d_in[4];
    const float* bi = (const float*)d_in[5];
    const float* Wd = (const float*)d_in[6];
    const float* bd = (const float*)d_in[7];
    float* out = (float*)d_out;

    static bool attr_done = false;
    if (!attr_done) {
        cudaFuncSetAttribute(lstm_scan, cudaFuncAttributeMaxDynamicSharedMemorySize, SMEM_TOTAL);
        cudaFuncSetAttribute(dense_mma, cudaFuncAttributeMaxDynamicSharedMemorySize, SMEM_TOTAL);
        attr_done = true;
    }

    void* p;
    cudaGetSymbolAddress(&p, g_wsum);  __half* wsum = (__half*)p;
    cudaGetSymbolAddress(&p, g_wcat);  __half* wcat = (__half*)p;
    cudaGetSymbolAddress(&p, g_xcat);  __half* xc   = (__half*)p;
    __half* xb0; __half* xb1;
    cudaGetSymbolAddress(&p, g_xa);    xb0 = (__half*)p;
    cudaGetSymbolAddress(&p, g_xb);    xb1 = (__half*)p;

    dim3 tb(32, 8);
    // launch order arranged so lstm_scan is the 4th kernel (ncu capture slot)
    prep_wsum<<<dim3(128, 32), tb>>>(W, U);
    prep_wcat<<<dim3(128, 64), tb>>>(W, U);
    prep_xc<<<2048, 256>>>(x0, h0);

    lstm_scan<<<NCTA, 256, SMEM_TOTAL>>>(xc, wcat, wsum, bi, c0, xb0, xb1);

    prep_wd<<<dim3(16, 32), tb>>>(Wd);       // independent of scan; needed by dense only
    dense_mma<<<dim3(4, 512), 256, SMEM_TOTAL>>>(bd, out);
}